// round 9
// baseline (speedup 1.0000x reference)
#include <cuda_runtime.h>
#include <math.h>
#include <float.h>

// Problem shape (fixed by the reference)
constexpr int B_ = 2;
constexpr int C_ = 16;
constexpr int D_ = 80;
constexpr int H_ = 96;
constexpr int W_ = 96;
constexpr int DHW = D_ * H_ * W_;             // 737280
constexpr int SP  = B_ * DHW;                 // 1474560
constexpr size_t TEN = (size_t)B_ * C_ * DHW; // elements per tensor

// Scratch: per gate, interleaved {max, avg} pairs. (float2)[gate][b*DHW + pos]
__device__ float g_pool[4 * SP];

typedef unsigned long long ull;

__device__ __forceinline__ void unpack2(float& lo, float& hi, ull v) {
    asm("mov.b64 {%0, %1}, %2;" : "=f"(lo), "=f"(hi) : "l"(v));
}
// packed dual-fp32 FMA: d = a*b + d
__device__ __forceinline__ void fma2(ull& d, ull a, ull b) {
    asm("fma.rn.f32x2 %0, %1, %2, %0;" : "+l"(d) : "l"(a), "l"(b));
}

// ---------------------------------------------------------------------------
// Kernel 1: channel max/avg pooling, writes {max,avg} interleaved per gate
// ---------------------------------------------------------------------------
__global__ __launch_bounds__(256)
void pool_kernel(const float* __restrict__ fix, const float* __restrict__ mov) {
    int g4 = blockIdx.x * blockDim.x + threadIdx.x;   // group of 4 positions
    constexpr int Q = DHW / 4;
    if (g4 >= SP / 4) return;
    int b  = g4 / Q;
    int s4 = g4 - b * Q;

    const float4* pf = reinterpret_cast<const float4*>(fix) + (size_t)b * C_ * Q + s4;
    const float4* pm = reinterpret_cast<const float4*>(mov) + (size_t)b * C_ * Q + s4;

    float4 mxf = make_float4(-FLT_MAX, -FLT_MAX, -FLT_MAX, -FLT_MAX);
    float4 mxm = mxf;
    float4 smf = make_float4(0.f, 0.f, 0.f, 0.f);
    float4 smm = smf;
#pragma unroll
    for (int c = 0; c < C_; c++) {
        float4 v = pf[(size_t)c * Q];
        mxf.x = fmaxf(mxf.x, v.x); mxf.y = fmaxf(mxf.y, v.y);
        mxf.z = fmaxf(mxf.z, v.z); mxf.w = fmaxf(mxf.w, v.w);
        smf.x += v.x; smf.y += v.y; smf.z += v.z; smf.w += v.w;
        float4 u = pm[(size_t)c * Q];
        mxm.x = fmaxf(mxm.x, u.x); mxm.y = fmaxf(mxm.y, u.y);
        mxm.z = fmaxf(mxm.z, u.z); mxm.w = fmaxf(mxm.w, u.w);
        smm.x += u.x; smm.y += u.y; smm.z += u.z; smm.w += u.w;
    }
    const float inv = 1.f / 16.f;

    float4* gp = reinterpret_cast<float4*>(g_pool);
    size_t base0 = ((size_t)0 * SP + (size_t)b * DHW) / 2 + 2 * (size_t)s4;
    size_t base1 = ((size_t)1 * SP + (size_t)b * DHW) / 2 + 2 * (size_t)s4;
    gp[base0 + 0] = make_float4(mxf.x, smf.x * inv, mxf.y, smf.y * inv);
    gp[base0 + 1] = make_float4(mxf.z, smf.z * inv, mxf.w, smf.w * inv);
    gp[base1 + 0] = make_float4(mxm.x, smm.x * inv, mxm.y, smm.y * inv);
    gp[base1 + 1] = make_float4(mxm.z, smm.z * inv, mxm.w, smm.w * inv);
}

// ---------------------------------------------------------------------------
// Kernel 2: 7x7x7 conv, plane-streamed halo, channel-paired f32x2
// Tile: 32(W) x 8(H) x 2(D), 32 threads (8,2,2), per-thread 4W x 4H x 1D
// One input z-plane in smem at a time (double-buffered cp.async ring).
// ---------------------------------------------------------------------------
constexpr int TW = 32, TH = 8, TD = 2;
constexpr int HXP = TW + 6;   // 38 pairs per halo row (38*8B = 304B, 16B-aligned)
constexpr int HY  = TH + 6;   // 14
constexpr int HZ  = TD + 6;   // 8 input planes per tile
constexpr int PLANE_P = HY * HXP;              // 532 pairs = 4256 B
constexpr int W_ULLS  = 7 * 7 * 8;             // padded weights [kz][ky][8]
constexpr int SMEM_BYTES = 2 * PLANE_P * 8 + W_ULLS * 8;   // 11648 B

__global__ void __launch_bounds__(32, 16)
conv_apply_kernel(const float* __restrict__ fix, const float* __restrict__ mov,
                  const float* __restrict__ w_f2m, const float* __restrict__ w_m2f,
                  float* __restrict__ out) {
    __shared__ float2 s_buf[2][PLANE_P];
    __shared__ ull    s_w2[W_ULLS];

    const int tx = threadIdx.x;          // 0..7  (4 W outputs)
    const int ty = (threadIdx.x >> 3) & 0; // unused placeholder
    const int t_y = threadIdx.y;         // 0..1  (4 H outputs)
    const int t_z = threadIdx.z;         // 0..1  (1 D output)
    const int tid = tx + t_y * 8 + t_z * 16;   // 0..31 (one warp)

    const int x0 = blockIdx.x * TW;
    const int y0 = blockIdx.y * TH;
    const int bz = blockIdx.z;                 // 0..159
    const int b  = bz / (D_ / TD);
    const int z0 = (bz - b * (D_ / TD)) * TD;

    float gsum[2][4][4];   // [gate][w][h]

#pragma unroll 1
    for (int g = 0; g < 2; g++) {
        const float2* src = reinterpret_cast<const float2*>(g_pool)
                          + (size_t)g * SP + (size_t)b * DHW;

        // ---- prefetch plane 0 ----
        {
            int gz = z0 - 3;
            bool pok = (unsigned)gz < (unsigned)D_;
            const float2* pl = src + (size_t)(pok ? gz : 0) * H_ * W_;
            for (int i = tid; i < PLANE_P; i += 32) {
                int dy = i / HXP, dx = i - dy * HXP;
                int gy = y0 + dy - 3, gx = x0 + dx - 3;
                bool ok = pok && ((unsigned)gy < (unsigned)H_) &&
                                 ((unsigned)gx < (unsigned)W_);
                unsigned sa = (unsigned)__cvta_generic_to_shared(&s_buf[0][i]);
                const float2* gp2 = pl + (ok ? (gy * W_ + gx) : 0);
                int nb = ok ? 8 : 0;
                asm volatile("cp.async.ca.shared.global [%0], [%1], 8, %2;"
                             :: "r"(sa), "l"(gp2), "r"(nb));
            }
            asm volatile("cp.async.commit_group;" ::: "memory");
        }

        // ---- paired weights into padded layout [kz][ky][8] ----
        const float* wsrc = (g == 0 ? w_f2m : w_m2f);
        for (int k = tid; k < 343; k += 32) {
            int kz  = k / 49;
            int rem = k - kz * 49;
            int ky  = rem / 7;
            int kx  = rem - ky * 7;
            reinterpret_cast<float2*>(s_w2)[kz * 56 + ky * 8 + kx] =
                make_float2(wsrc[k], wsrc[343 + k]);
        }

        ull pacc[4][4];
#pragma unroll
        for (int w = 0; w < 4; w++)
#pragma unroll
            for (int h = 0; h < 4; h++) pacc[w][h] = 0ull;

        // ---- stream input planes ----
#pragma unroll 1
        for (int p = 0; p < HZ; p++) {
            __syncwarp();   // prior compute done before overwriting other buffer
            if (p + 1 < HZ) {
                int gz = z0 + (p + 1) - 3;
                bool pok = (unsigned)gz < (unsigned)D_;
                const float2* pl = src + (size_t)(pok ? gz : 0) * H_ * W_;
                float2* dstb = s_buf[(p + 1) & 1];
                for (int i = tid; i < PLANE_P; i += 32) {
                    int dy = i / HXP, dx = i - dy * HXP;
                    int gy = y0 + dy - 3, gx = x0 + dx - 3;
                    bool ok = pok && ((unsigned)gy < (unsigned)H_) &&
                                     ((unsigned)gx < (unsigned)W_);
                    unsigned sa = (unsigned)__cvta_generic_to_shared(&dstb[i]);
                    const float2* gp2 = pl + (ok ? (gy * W_ + gx) : 0);
                    int nb = ok ? 8 : 0;
                    asm volatile("cp.async.ca.shared.global [%0], [%1], 8, %2;"
                                 :: "r"(sa), "l"(gp2), "r"(nb));
                }
                asm volatile("cp.async.commit_group;" ::: "memory");
                asm volatile("cp.async.wait_group 1;" ::: "memory");
            } else {
                asm volatile("cp.async.wait_group 0;" ::: "memory");
            }
            __syncwarp();   // plane p visible to all lanes

            // ---- compute: kz = p - t_z for this thread's output plane ----
            const int kz = p - t_z;
            if ((unsigned)kz <= 6u) {
                const float2* buf = s_buf[p & 1] + (size_t)t_y * 4 * HXP + tx * 4;
                const ull*    wz  = s_w2 + kz * 56;
#pragma unroll
                for (int r = 0; r < 10; r++) {
                    const float2* pr = buf + r * HXP;
                    ulonglong2 q0 = *reinterpret_cast<const ulonglong2*>(pr);
                    ulonglong2 q1 = *reinterpret_cast<const ulonglong2*>(pr + 2);
                    ulonglong2 q2 = *reinterpret_cast<const ulonglong2*>(pr + 4);
                    ulonglong2 q3 = *reinterpret_cast<const ulonglong2*>(pr + 6);
                    ulonglong2 q4 = *reinterpret_cast<const ulonglong2*>(pr + 8);
                    ull pk[10] = {q0.x, q0.y, q1.x, q1.y, q2.x,
                                  q2.y, q3.x, q3.y, q4.x, q4.y};
#pragma unroll
                    for (int h = 0; h < 4; h++) {
                        const int ky = r - h;
                        if (ky >= 0 && ky <= 6) {
                            const ull* wr = wz + ky * 8;   // 16B-aligned row
                            ulonglong2 a0 = *reinterpret_cast<const ulonglong2*>(wr);
                            ulonglong2 a1 = *reinterpret_cast<const ulonglong2*>(wr + 2);
                            ulonglong2 a2 = *reinterpret_cast<const ulonglong2*>(wr + 4);
                            ull w6 = wr[6];
                            ull wk[7] = {a0.x, a0.y, a1.x, a1.y, a2.x, a2.y, w6};
#pragma unroll
                            for (int kx = 0; kx < 7; kx++) {
                                ull wv = wk[kx];
#pragma unroll
                                for (int w = 0; w < 4; w++)
                                    fma2(pacc[w][h], pk[kx + w], wv);
                            }
                        }
                    }
                }
            }
        }

        // ---- reduce channel pair: conv = lo + hi ----
#pragma unroll
        for (int w = 0; w < 4; w++)
#pragma unroll
            for (int h = 0; h < 4; h++) {
                float lo, hi;
                unpack2(lo, hi, pacc[w][h]);
                gsum[g][w][h] = lo + hi;
            }
        __syncwarp();   // weights buffer reused by next gate
    }

    // ---- sigmoid gates ----
    float gf[4][4], gm[4][4];
#pragma unroll
    for (int w = 0; w < 4; w++)
#pragma unroll
        for (int h = 0; h < 4; h++) {
            gf[w][h] = 1.f / (1.f + __expf(-gsum[0][w][h]));
            gm[w][h] = 1.f / (1.f + __expf(-gsum[1][w][h]));
        }

    // ---- apply: fix_out = mov*sa_fix + fix ; move_out = fix*sa_move + mov ----
    const int z  = z0 + t_z;
    const int yb = y0 + t_y * 4;
    const int x  = x0 + tx * 4;
    const size_t sbase = (size_t)b * C_ * DHW + (size_t)z * H_ * W_ + (size_t)yb * W_ + x;
    float* out_f = out;
    float* out_m = out + TEN;

#pragma unroll 2
    for (int c = 0; c < C_; c++) {
        size_t oc = sbase + (size_t)c * DHW;
#pragma unroll
        for (int h = 0; h < 4; h++) {
            size_t o = oc + (size_t)h * W_;
            float4 f = *reinterpret_cast<const float4*>(fix + o);
            float4 m = *reinterpret_cast<const float4*>(mov + o);
            float4 of, om;
            of.x = fmaf(m.x, gf[0][h], f.x);  om.x = fmaf(f.x, gm[0][h], m.x);
            of.y = fmaf(m.y, gf[1][h], f.y);  om.y = fmaf(f.y, gm[1][h], m.y);
            of.z = fmaf(m.z, gf[2][h], f.z);  om.z = fmaf(f.z, gm[2][h], m.z);
            of.w = fmaf(m.w, gf[3][h], f.w);  om.w = fmaf(f.w, gm[3][h], m.w);
            *reinterpret_cast<float4*>(out_f + o) = of;
            *reinterpret_cast<float4*>(out_m + o) = om;
        }
    }
}

// ---------------------------------------------------------------------------
extern "C" void kernel_launch(void* const* d_in, const int* in_sizes, int n_in,
                              void* d_out, int out_size) {
    const float* fix   = (const float*)d_in[0];
    const float* mov   = (const float*)d_in[1];
    const float* w_f2m = (const float*)d_in[2];
    const float* w_m2f = (const float*)d_in[3];
    float* out = (float*)d_out;

    // Pass 1: pooling (writes channel-interleaved pairs)
    {
        int threads = 256;
        int blocks = (SP / 4 + threads - 1) / threads;
        pool_kernel<<<blocks, threads>>>(fix, mov);
    }
    // Pass 2: conv + sigmoid + gated residual
    {
        dim3 block(8, 2, 2);                              // 32 threads = 1 warp
        dim3 grid(W_ / TW, H_ / TH, B_ * (D_ / TD));      // 3 x 12 x 80 = 2880
        conv_apply_kernel<<<grid, block>>>(fix, mov, w_f2m, w_m2f, out);
    }
}

// round 10
// speedup vs baseline: 1.0003x; 1.0003x over previous
#include <cuda_runtime.h>
#include <math.h>
#include <float.h>

// Problem shape (fixed by the reference)
constexpr int B_ = 2;
constexpr int C_ = 16;
constexpr int D_ = 80;
constexpr int H_ = 96;
constexpr int W_ = 96;
constexpr int DHW = D_ * H_ * W_;             // 737280
constexpr int SP  = B_ * DHW;                 // 1474560
constexpr size_t TEN = (size_t)B_ * C_ * DHW; // elements per tensor

// Scratch: per gate, interleaved {max, avg} pairs. (float2)[gate][b*DHW + pos]
__device__ float g_pool[4 * SP];

typedef unsigned long long ull;

__device__ __forceinline__ void unpack2(float& lo, float& hi, ull v) {
    asm("mov.b64 {%0, %1}, %2;" : "=f"(lo), "=f"(hi) : "l"(v));
}
// packed dual-fp32 FMA: d = a*b + d
__device__ __forceinline__ void fma2(ull& d, ull a, ull b) {
    asm("fma.rn.f32x2 %0, %1, %2, %0;" : "+l"(d) : "l"(a), "l"(b));
}

// ---------------------------------------------------------------------------
// Kernel 1: channel max/avg pooling, writes {max,avg} interleaved per gate
// ---------------------------------------------------------------------------
__global__ __launch_bounds__(256)
void pool_kernel(const float* __restrict__ fix, const float* __restrict__ mov) {
    int g4 = blockIdx.x * blockDim.x + threadIdx.x;   // group of 4 positions
    constexpr int Q = DHW / 4;
    if (g4 >= SP / 4) return;
    int b  = g4 / Q;
    int s4 = g4 - b * Q;

    const float4* pf = reinterpret_cast<const float4*>(fix) + (size_t)b * C_ * Q + s4;
    const float4* pm = reinterpret_cast<const float4*>(mov) + (size_t)b * C_ * Q + s4;

    float4 mxf = make_float4(-FLT_MAX, -FLT_MAX, -FLT_MAX, -FLT_MAX);
    float4 mxm = mxf;
    float4 smf = make_float4(0.f, 0.f, 0.f, 0.f);
    float4 smm = smf;
#pragma unroll
    for (int c = 0; c < C_; c++) {
        float4 v = pf[(size_t)c * Q];
        mxf.x = fmaxf(mxf.x, v.x); mxf.y = fmaxf(mxf.y, v.y);
        mxf.z = fmaxf(mxf.z, v.z); mxf.w = fmaxf(mxf.w, v.w);
        smf.x += v.x; smf.y += v.y; smf.z += v.z; smf.w += v.w;
        float4 u = pm[(size_t)c * Q];
        mxm.x = fmaxf(mxm.x, u.x); mxm.y = fmaxf(mxm.y, u.y);
        mxm.z = fmaxf(mxm.z, u.z); mxm.w = fmaxf(mxm.w, u.w);
        smm.x += u.x; smm.y += u.y; smm.z += u.z; smm.w += u.w;
    }
    const float inv = 1.f / 16.f;

    float4* gp = reinterpret_cast<float4*>(g_pool);
    size_t base0 = ((size_t)0 * SP + (size_t)b * DHW) / 2 + 2 * (size_t)s4;
    size_t base1 = ((size_t)1 * SP + (size_t)b * DHW) / 2 + 2 * (size_t)s4;
    gp[base0 + 0] = make_float4(mxf.x, smf.x * inv, mxf.y, smf.y * inv);
    gp[base0 + 1] = make_float4(mxf.z, smf.z * inv, mxf.w, smf.w * inv);
    gp[base1 + 0] = make_float4(mxm.x, smm.x * inv, mxm.y, smm.y * inv);
    gp[base1 + 1] = make_float4(mxm.z, smm.z * inv, mxm.w, smm.w * inv);
}

// ---------------------------------------------------------------------------
// Kernel 2: 7x7x7 conv, plane-streamed halo, channel-paired f32x2
// Tile: 32(W) x 8(H) x 2(D), 32 threads (8,2,2), per-thread 4W x 4H x 1D
// One input z-plane in smem at a time (double-buffered cp.async ring).
// ---------------------------------------------------------------------------
constexpr int TW = 32, TH = 8, TD = 2;
constexpr int HXP = TW + 6;   // 38 pairs per halo row (38*8B = 304B, 16B-aligned)
constexpr int HY  = TH + 6;   // 14
constexpr int HZ  = TD + 6;   // 8 input planes per tile
constexpr int PLANE_P = HY * HXP;              // 532 pairs = 4256 B
constexpr int W_ULLS  = 7 * 7 * 8;             // padded weights [kz][ky][8]
constexpr int SMEM_BYTES = 2 * PLANE_P * 8 + W_ULLS * 8;   // 11648 B

__global__ void __launch_bounds__(32, 16)
conv_apply_kernel(const float* __restrict__ fix, const float* __restrict__ mov,
                  const float* __restrict__ w_f2m, const float* __restrict__ w_m2f,
                  float* __restrict__ out) {
    __shared__ float2 s_buf[2][PLANE_P];
    __shared__ ull    s_w2[W_ULLS];

    const int tx = threadIdx.x;          // 0..7  (4 W outputs)
    const int ty = (threadIdx.x >> 3) & 0; // unused placeholder
    const int t_y = threadIdx.y;         // 0..1  (4 H outputs)
    const int t_z = threadIdx.z;         // 0..1  (1 D output)
    const int tid = tx + t_y * 8 + t_z * 16;   // 0..31 (one warp)

    const int x0 = blockIdx.x * TW;
    const int y0 = blockIdx.y * TH;
    const int bz = blockIdx.z;                 // 0..159
    const int b  = bz / (D_ / TD);
    const int z0 = (bz - b * (D_ / TD)) * TD;

    float gsum[2][4][4];   // [gate][w][h]

#pragma unroll 1
    for (int g = 0; g < 2; g++) {
        const float2* src = reinterpret_cast<const float2*>(g_pool)
                          + (size_t)g * SP + (size_t)b * DHW;

        // ---- prefetch plane 0 ----
        {
            int gz = z0 - 3;
            bool pok = (unsigned)gz < (unsigned)D_;
            const float2* pl = src + (size_t)(pok ? gz : 0) * H_ * W_;
            for (int i = tid; i < PLANE_P; i += 32) {
                int dy = i / HXP, dx = i - dy * HXP;
                int gy = y0 + dy - 3, gx = x0 + dx - 3;
                bool ok = pok && ((unsigned)gy < (unsigned)H_) &&
                                 ((unsigned)gx < (unsigned)W_);
                unsigned sa = (unsigned)__cvta_generic_to_shared(&s_buf[0][i]);
                const float2* gp2 = pl + (ok ? (gy * W_ + gx) : 0);
                int nb = ok ? 8 : 0;
                asm volatile("cp.async.ca.shared.global [%0], [%1], 8, %2;"
                             :: "r"(sa), "l"(gp2), "r"(nb));
            }
            asm volatile("cp.async.commit_group;" ::: "memory");
        }

        // ---- paired weights into padded layout [kz][ky][8] ----
        const float* wsrc = (g == 0 ? w_f2m : w_m2f);
        for (int k = tid; k < 343; k += 32) {
            int kz  = k / 49;
            int rem = k - kz * 49;
            int ky  = rem / 7;
            int kx  = rem - ky * 7;
            reinterpret_cast<float2*>(s_w2)[kz * 56 + ky * 8 + kx] =
                make_float2(wsrc[k], wsrc[343 + k]);
        }

        ull pacc[4][4];
#pragma unroll
        for (int w = 0; w < 4; w++)
#pragma unroll
            for (int h = 0; h < 4; h++) pacc[w][h] = 0ull;

        // ---- stream input planes ----
#pragma unroll 1
        for (int p = 0; p < HZ; p++) {
            __syncwarp();   // prior compute done before overwriting other buffer
            if (p + 1 < HZ) {
                int gz = z0 + (p + 1) - 3;
                bool pok = (unsigned)gz < (unsigned)D_;
                const float2* pl = src + (size_t)(pok ? gz : 0) * H_ * W_;
                float2* dstb = s_buf[(p + 1) & 1];
                for (int i = tid; i < PLANE_P; i += 32) {
                    int dy = i / HXP, dx = i - dy * HXP;
                    int gy = y0 + dy - 3, gx = x0 + dx - 3;
                    bool ok = pok && ((unsigned)gy < (unsigned)H_) &&
                                     ((unsigned)gx < (unsigned)W_);
                    unsigned sa = (unsigned)__cvta_generic_to_shared(&dstb[i]);
                    const float2* gp2 = pl + (ok ? (gy * W_ + gx) : 0);
                    int nb = ok ? 8 : 0;
                    asm volatile("cp.async.ca.shared.global [%0], [%1], 8, %2;"
                                 :: "r"(sa), "l"(gp2), "r"(nb));
                }
                asm volatile("cp.async.commit_group;" ::: "memory");
                asm volatile("cp.async.wait_group 1;" ::: "memory");
            } else {
                asm volatile("cp.async.wait_group 0;" ::: "memory");
            }
            __syncwarp();   // plane p visible to all lanes

            // ---- compute: kz = p - t_z for this thread's output plane ----
            const int kz = p - t_z;
            if ((unsigned)kz <= 6u) {
                const float2* buf = s_buf[p & 1] + (size_t)t_y * 4 * HXP + tx * 4;
                const ull*    wz  = s_w2 + kz * 56;
#pragma unroll
                for (int r = 0; r < 10; r++) {
                    const float2* pr = buf + r * HXP;
                    ulonglong2 q0 = *reinterpret_cast<const ulonglong2*>(pr);
                    ulonglong2 q1 = *reinterpret_cast<const ulonglong2*>(pr + 2);
                    ulonglong2 q2 = *reinterpret_cast<const ulonglong2*>(pr + 4);
                    ulonglong2 q3 = *reinterpret_cast<const ulonglong2*>(pr + 6);
                    ulonglong2 q4 = *reinterpret_cast<const ulonglong2*>(pr + 8);
                    ull pk[10] = {q0.x, q0.y, q1.x, q1.y, q2.x,
                                  q2.y, q3.x, q3.y, q4.x, q4.y};
#pragma unroll
                    for (int h = 0; h < 4; h++) {
                        const int ky = r - h;
                        if (ky >= 0 && ky <= 6) {
                            const ull* wr = wz + ky * 8;   // 16B-aligned row
                            ulonglong2 a0 = *reinterpret_cast<const ulonglong2*>(wr);
                            ulonglong2 a1 = *reinterpret_cast<const ulonglong2*>(wr + 2);
                            ulonglong2 a2 = *reinterpret_cast<const ulonglong2*>(wr + 4);
                            ull w6 = wr[6];
                            ull wk[7] = {a0.x, a0.y, a1.x, a1.y, a2.x, a2.y, w6};
#pragma unroll
                            for (int kx = 0; kx < 7; kx++) {
                                ull wv = wk[kx];
#pragma unroll
                                for (int w = 0; w < 4; w++)
                                    fma2(pacc[w][h], pk[kx + w], wv);
                            }
                        }
                    }
                }
            }
        }

        // ---- reduce channel pair: conv = lo + hi ----
#pragma unroll
        for (int w = 0; w < 4; w++)
#pragma unroll
            for (int h = 0; h < 4; h++) {
                float lo, hi;
                unpack2(lo, hi, pacc[w][h]);
                gsum[g][w][h] = lo + hi;
            }
        __syncwarp();   // weights buffer reused by next gate
    }

    // ---- sigmoid gates ----
    float gf[4][4], gm[4][4];
#pragma unroll
    for (int w = 0; w < 4; w++)
#pragma unroll
        for (int h = 0; h < 4; h++) {
            gf[w][h] = 1.f / (1.f + __expf(-gsum[0][w][h]));
            gm[w][h] = 1.f / (1.f + __expf(-gsum[1][w][h]));
        }

    // ---- apply: fix_out = mov*sa_fix + fix ; move_out = fix*sa_move + mov ----
    const int z  = z0 + t_z;
    const int yb = y0 + t_y * 4;
    const int x  = x0 + tx * 4;
    const size_t sbase = (size_t)b * C_ * DHW + (size_t)z * H_ * W_ + (size_t)yb * W_ + x;
    float* out_f = out;
    float* out_m = out + TEN;

#pragma unroll 2
    for (int c = 0; c < C_; c++) {
        size_t oc = sbase + (size_t)c * DHW;
#pragma unroll
        for (int h = 0; h < 4; h++) {
            size_t o = oc + (size_t)h * W_;
            float4 f = *reinterpret_cast<const float4*>(fix + o);
            float4 m = *reinterpret_cast<const float4*>(mov + o);
            float4 of, om;
            of.x = fmaf(m.x, gf[0][h], f.x);  om.x = fmaf(f.x, gm[0][h], m.x);
            of.y = fmaf(m.y, gf[1][h], f.y);  om.y = fmaf(f.y, gm[1][h], m.y);
            of.z = fmaf(m.z, gf[2][h], f.z);  om.z = fmaf(f.z, gm[2][h], m.z);
            of.w = fmaf(m.w, gf[3][h], f.w);  om.w = fmaf(f.w, gm[3][h], m.w);
            *reinterpret_cast<float4*>(out_f + o) = of;
            *reinterpret_cast<float4*>(out_m + o) = om;
        }
    }
}

// ---------------------------------------------------------------------------
extern "C" void kernel_launch(void* const* d_in, const int* in_sizes, int n_in,
                              void* d_out, int out_size) {
    const float* fix   = (const float*)d_in[0];
    const float* mov   = (const float*)d_in[1];
    const float* w_f2m = (const float*)d_in[2];
    const float* w_m2f = (const float*)d_in[3];
    float* out = (float*)d_out;

    // Pass 1: pooling (writes channel-interleaved pairs)
    {
        int threads = 256;
        int blocks = (SP / 4 + threads - 1) / threads;
        pool_kernel<<<blocks, threads>>>(fix, mov);
    }
    // Pass 2: conv + sigmoid + gated residual
    {
        dim3 block(8, 2, 2);                              // 32 threads = 1 warp
        dim3 grid(W_ / TW, H_ / TH, B_ * (D_ / TD));      // 3 x 12 x 80 = 2880
        conv_apply_kernel<<<grid, block>>>(fix, mov, w_f2m, w_m2f, out);
    }
}

// round 11
// speedup vs baseline: 1.1599x; 1.1595x over previous
#include <cuda_runtime.h>
#include <math.h>
#include <float.h>

// Problem shape (fixed by the reference)
constexpr int B_ = 2;
constexpr int C_ = 16;
constexpr int D_ = 80;
constexpr int H_ = 96;
constexpr int W_ = 96;
constexpr int DHW = D_ * H_ * W_;             // 737280
constexpr int SP  = B_ * DHW;                 // 1474560
constexpr size_t TEN = (size_t)B_ * C_ * DHW; // elements per tensor

// Scratch: per gate, interleaved {max, avg} pairs. (float2)[gate][b*DHW + pos]
__device__ float g_pool[4 * SP];

typedef unsigned long long ull;

__device__ __forceinline__ void unpack2(float& lo, float& hi, ull v) {
    asm("mov.b64 {%0, %1}, %2;" : "=f"(lo), "=f"(hi) : "l"(v));
}
// packed dual-fp32 FMA: d = a*b + d
__device__ __forceinline__ void fma2(ull& d, ull a, ull b) {
    asm("fma.rn.f32x2 %0, %1, %2, %0;" : "+l"(d) : "l"(a), "l"(b));
}

// ---------------------------------------------------------------------------
// Kernel 1: channel max/avg pooling, writes {max,avg} interleaved per gate
// ---------------------------------------------------------------------------
__global__ __launch_bounds__(256)
void pool_kernel(const float* __restrict__ fix, const float* __restrict__ mov) {
    int g4 = blockIdx.x * blockDim.x + threadIdx.x;   // group of 4 positions
    constexpr int Q = DHW / 4;
    if (g4 >= SP / 4) return;
    int b  = g4 / Q;
    int s4 = g4 - b * Q;

    const float4* pf = reinterpret_cast<const float4*>(fix) + (size_t)b * C_ * Q + s4;
    const float4* pm = reinterpret_cast<const float4*>(mov) + (size_t)b * C_ * Q + s4;

    float4 mxf = make_float4(-FLT_MAX, -FLT_MAX, -FLT_MAX, -FLT_MAX);
    float4 mxm = mxf;
    float4 smf = make_float4(0.f, 0.f, 0.f, 0.f);
    float4 smm = smf;
#pragma unroll
    for (int c = 0; c < C_; c++) {
        float4 v = pf[(size_t)c * Q];
        mxf.x = fmaxf(mxf.x, v.x); mxf.y = fmaxf(mxf.y, v.y);
        mxf.z = fmaxf(mxf.z, v.z); mxf.w = fmaxf(mxf.w, v.w);
        smf.x += v.x; smf.y += v.y; smf.z += v.z; smf.w += v.w;
        float4 u = pm[(size_t)c * Q];
        mxm.x = fmaxf(mxm.x, u.x); mxm.y = fmaxf(mxm.y, u.y);
        mxm.z = fmaxf(mxm.z, u.z); mxm.w = fmaxf(mxm.w, u.w);
        smm.x += u.x; smm.y += u.y; smm.z += u.z; smm.w += u.w;
    }
    const float inv = 1.f / 16.f;

    float4* gp = reinterpret_cast<float4*>(g_pool);
    size_t base0 = ((size_t)0 * SP + (size_t)b * DHW) / 2 + 2 * (size_t)s4;
    size_t base1 = ((size_t)1 * SP + (size_t)b * DHW) / 2 + 2 * (size_t)s4;
    gp[base0 + 0] = make_float4(mxf.x, smf.x * inv, mxf.y, smf.y * inv);
    gp[base0 + 1] = make_float4(mxf.z, smf.z * inv, mxf.w, smf.w * inv);
    gp[base1 + 0] = make_float4(mxm.x, smm.x * inv, mxm.y, smm.y * inv);
    gp[base1 + 1] = make_float4(mxm.z, smm.z * inv, mxm.w, smm.w * inv);
}

// ---------------------------------------------------------------------------
// Kernel 2: 7x7x7 conv (channel-paired f32x2, row-streamed) + sigmoid + apply
// Tile: 32(W) x 16(H) x 2(D), 128 threads (16,4,2), per-thread 2W x 4H x 1D
// 16-lane W split -> 16B lane stride -> conflict-free LDS.128, dense rows.
// 56.6 KB smem -> 4 CTAs/SM (16 warps).
// ---------------------------------------------------------------------------
constexpr int TW = 32, TH = 16, TD = 2;
constexpr int HXP = TW + 6;   // 38 pairs per halo row (304B, 16B-aligned)
constexpr int HY  = TH + 6;   // 22
constexpr int HZ  = TD + 6;   // 8
constexpr int HALO_P = HZ * HY * HXP;             // 6688 pairs = 53504 B
constexpr int W_ULLS = 7 * 7 * 8;                 // padded weights [kz][ky][8]
constexpr int SMEM_BYTES = HALO_P * 8 + W_ULLS * 8;   // 56640 B

__global__ void __launch_bounds__(128, 4)
conv_apply_kernel(const float* __restrict__ fix, const float* __restrict__ mov,
                  const float* __restrict__ w_f2m, const float* __restrict__ w_m2f,
                  float* __restrict__ out) {
    extern __shared__ float2 smem2[];
    float2* s_h  = smem2;                                   // [HZ][HY][HXP]
    ull*    s_w2 = reinterpret_cast<ull*>(smem2 + HALO_P);  // padded weight pairs

    const int tx = threadIdx.x;      // 0..15 (2 W outputs)
    const int ty = threadIdx.y;      // 0..3  (4 H outputs)
    const int tz = threadIdx.z;      // 0..1  (1 D output)
    const int tid = tx + ty * 16 + tz * 64;

    const int x0 = blockIdx.x * TW;
    const int y0 = blockIdx.y * TH;
    const int bz = blockIdx.z;                 // 0..79
    const int b  = bz / (D_ / TD);
    const int z0 = (bz - b * (D_ / TD)) * TD;

    const unsigned s_h_sa = (unsigned)__cvta_generic_to_shared(s_h);

    float gf[2][4], gm[2][4];   // sigmoid gates per gate, [w][h]

#pragma unroll 1
    for (int g = 0; g < 2; g++) {
        // ---- halo via cp.async (zfill for OOB) ----
        const float2* src = reinterpret_cast<const float2*>(g_pool)
                          + (size_t)g * SP + (size_t)b * DHW;
        for (int i = tid; i < HALO_P; i += 128) {
            int dz  = i / (HY * HXP);
            int rem = i - dz * (HY * HXP);
            int dy  = rem / HXP;
            int dx  = rem - dy * HXP;
            int gz = z0 + dz - 3, gy = y0 + dy - 3, gx = x0 + dx - 3;
            bool ok = ((unsigned)gz < (unsigned)D_) &&
                      ((unsigned)gy < (unsigned)H_) &&
                      ((unsigned)gx < (unsigned)W_);
            int off = ok ? ((gz * H_ + gy) * W_ + gx) : 0;
            unsigned sa = s_h_sa + (unsigned)(i * 8);
            int nb = ok ? 8 : 0;
            asm volatile("cp.async.ca.shared.global [%0], [%1], 8, %2;"
                         :: "r"(sa), "l"(src + off), "r"(nb));
        }
        asm volatile("cp.async.commit_group;" ::: "memory");

        // ---- paired weights into padded layout [kz][ky][8] ----
        const float* wsrc = (g == 0 ? w_f2m : w_m2f);
        for (int k = tid; k < 343; k += 128) {
            int kz  = k / 49;
            int rem = k - kz * 49;
            int ky  = rem / 7;
            int kx  = rem - ky * 7;
            reinterpret_cast<float2*>(s_w2)[kz * 56 + ky * 8 + kx] =
                make_float2(wsrc[k], wsrc[343 + k]);
        }
        asm volatile("cp.async.wait_group 0;" ::: "memory");
        __syncthreads();

        // ---- conv: stream rows, channel-paired FFMA2 ----
        ull pacc[2][4];   // [w][h]
#pragma unroll
        for (int w = 0; w < 2; w++)
#pragma unroll
            for (int h = 0; h < 4; h++) pacc[w][h] = 0ull;

#pragma unroll 1
        for (int kz = 0; kz < 7; kz++) {
            const float2* plane = s_h + (((size_t)tz + kz) * HY + ty * 4) * HXP + tx * 2;
            const ull*    wz    = s_w2 + kz * 56;
#pragma unroll
            for (int r = 0; r < 10; r++) {
                const float2* p = plane + r * HXP;
                // 8 pairs = 4 x LDS.128, lane stride 16B -> conflict-free
                ulonglong2 q0 = *reinterpret_cast<const ulonglong2*>(p);
                ulonglong2 q1 = *reinterpret_cast<const ulonglong2*>(p + 2);
                ulonglong2 q2 = *reinterpret_cast<const ulonglong2*>(p + 4);
                ulonglong2 q3 = *reinterpret_cast<const ulonglong2*>(p + 6);
                ull pk[8] = {q0.x, q0.y, q1.x, q1.y, q2.x, q2.y, q3.x, q3.y};
#pragma unroll
                for (int h = 0; h < 4; h++) {
                    const int ky = r - h;
                    if (ky >= 0 && ky <= 6) {
                        const ull* wr = wz + ky * 8;   // 16B-aligned row
                        ulonglong2 a0 = *reinterpret_cast<const ulonglong2*>(wr);
                        ulonglong2 a1 = *reinterpret_cast<const ulonglong2*>(wr + 2);
                        ulonglong2 a2 = *reinterpret_cast<const ulonglong2*>(wr + 4);
                        ull w6 = wr[6];
                        ull wk[7] = {a0.x, a0.y, a1.x, a1.y, a2.x, a2.y, w6};
#pragma unroll
                        for (int kx = 0; kx < 7; kx++) {
                            ull wv = wk[kx];
#pragma unroll
                            for (int w = 0; w < 2; w++)
                                fma2(pacc[w][h], pk[kx + w], wv);
                        }
                    }
                }
            }
        }

        // ---- reduce channel pair + sigmoid immediately (frees pacc regs) ----
#pragma unroll
        for (int w = 0; w < 2; w++)
#pragma unroll
            for (int h = 0; h < 4; h++) {
                float lo, hi;
                unpack2(lo, hi, pacc[w][h]);
                float s = 1.f / (1.f + __expf(-(lo + hi)));
                if (g == 0) gf[w][h] = s;
                else        gm[w][h] = s;
            }

        __syncthreads();   // protect smem before next gate overwrites
    }

    // ---- apply: fix_out = mov*sa_fix + fix ; move_out = fix*sa_move + mov ----
    const int z  = z0 + tz;
    const int yb = y0 + ty * 4;
    const int x  = x0 + tx * 2;
    const size_t sbase = (size_t)b * C_ * DHW + (size_t)z * H_ * W_ + (size_t)yb * W_ + x;
    float* out_f = out;
    float* out_m = out + TEN;

#pragma unroll 2
    for (int c = 0; c < C_; c++) {
        size_t oc = sbase + (size_t)c * DHW;
#pragma unroll
        for (int h = 0; h < 4; h++) {
            size_t o = oc + (size_t)h * W_;
            float2 f = *reinterpret_cast<const float2*>(fix + o);
            float2 m = *reinterpret_cast<const float2*>(mov + o);
            float2 of, om;
            of.x = fmaf(m.x, gf[0][h], f.x);  om.x = fmaf(f.x, gm[0][h], m.x);
            of.y = fmaf(m.y, gf[1][h], f.y);  om.y = fmaf(f.y, gm[1][h], m.y);
            *reinterpret_cast<float2*>(out_f + o) = of;
            *reinterpret_cast<float2*>(out_m + o) = om;
        }
    }
}

// ---------------------------------------------------------------------------
extern "C" void kernel_launch(void* const* d_in, const int* in_sizes, int n_in,
                              void* d_out, int out_size) {
    const float* fix   = (const float*)d_in[0];
    const float* mov   = (const float*)d_in[1];
    const float* w_f2m = (const float*)d_in[2];
    const float* w_m2f = (const float*)d_in[3];
    float* out = (float*)d_out;

    static bool attr_set = false;
    if (!attr_set) {
        cudaFuncSetAttribute(conv_apply_kernel,
                             cudaFuncAttributeMaxDynamicSharedMemorySize, SMEM_BYTES);
        attr_set = true;
    }

    // Pass 1: pooling (writes channel-interleaved pairs)
    {
        int threads = 256;
        int blocks = (SP / 4 + threads - 1) / threads;
        pool_kernel<<<blocks, threads>>>(fix, mov);
    }
    // Pass 2: conv + sigmoid + gated residual
    {
        dim3 block(16, 4, 2);                             // 128 threads
        dim3 grid(W_ / TW, H_ / TH, B_ * (D_ / TD));      // 3 x 6 x 80 = 1440
        conv_apply_kernel<<<grid, block, SMEM_BYTES>>>(fix, mov, w_f2m, w_m2f, out);
    }
}

// round 12
// speedup vs baseline: 1.1680x; 1.0070x over previous
#include <cuda_runtime.h>
#include <math.h>
#include <float.h>

// Problem shape (fixed by the reference)
constexpr int B_ = 2;
constexpr int C_ = 16;
constexpr int D_ = 80;
constexpr int H_ = 96;
constexpr int W_ = 96;
constexpr int DHW = D_ * H_ * W_;             // 737280
constexpr int SP  = B_ * DHW;                 // 1474560
constexpr size_t TEN = (size_t)B_ * C_ * DHW; // elements per tensor

// Scratch: per gate, interleaved {max, avg} pairs. (float2)[gate][b*DHW + pos]
__device__ float g_pool[4 * SP];

typedef unsigned long long ull;

__device__ __forceinline__ void unpack2(float& lo, float& hi, ull v) {
    asm("mov.b64 {%0, %1}, %2;" : "=f"(lo), "=f"(hi) : "l"(v));
}
// packed dual-fp32 FMA: d = a*b + d
__device__ __forceinline__ void fma2(ull& d, ull a, ull b) {
    asm("fma.rn.f32x2 %0, %1, %2, %0;" : "+l"(d) : "l"(a), "l"(b));
}

// ---------------------------------------------------------------------------
// Kernel 1: channel max/avg pooling, writes {max,avg} interleaved per gate
// ---------------------------------------------------------------------------
__global__ __launch_bounds__(256)
void pool_kernel(const float* __restrict__ fix, const float* __restrict__ mov) {
    int g4 = blockIdx.x * blockDim.x + threadIdx.x;   // group of 4 positions
    constexpr int Q = DHW / 4;
    if (g4 >= SP / 4) return;
    int b  = g4 / Q;
    int s4 = g4 - b * Q;

    const float4* pf = reinterpret_cast<const float4*>(fix) + (size_t)b * C_ * Q + s4;
    const float4* pm = reinterpret_cast<const float4*>(mov) + (size_t)b * C_ * Q + s4;

    float4 mxf = make_float4(-FLT_MAX, -FLT_MAX, -FLT_MAX, -FLT_MAX);
    float4 mxm = mxf;
    float4 smf = make_float4(0.f, 0.f, 0.f, 0.f);
    float4 smm = smf;
#pragma unroll
    for (int c = 0; c < C_; c++) {
        float4 v = pf[(size_t)c * Q];
        mxf.x = fmaxf(mxf.x, v.x); mxf.y = fmaxf(mxf.y, v.y);
        mxf.z = fmaxf(mxf.z, v.z); mxf.w = fmaxf(mxf.w, v.w);
        smf.x += v.x; smf.y += v.y; smf.z += v.z; smf.w += v.w;
        float4 u = pm[(size_t)c * Q];
        mxm.x = fmaxf(mxm.x, u.x); mxm.y = fmaxf(mxm.y, u.y);
        mxm.z = fmaxf(mxm.z, u.z); mxm.w = fmaxf(mxm.w, u.w);
        smm.x += u.x; smm.y += u.y; smm.z += u.z; smm.w += u.w;
    }
    const float inv = 1.f / 16.f;

    float4* gp = reinterpret_cast<float4*>(g_pool);
    size_t base0 = ((size_t)0 * SP + (size_t)b * DHW) / 2 + 2 * (size_t)s4;
    size_t base1 = ((size_t)1 * SP + (size_t)b * DHW) / 2 + 2 * (size_t)s4;
    gp[base0 + 0] = make_float4(mxf.x, smf.x * inv, mxf.y, smf.y * inv);
    gp[base0 + 1] = make_float4(mxf.z, smf.z * inv, mxf.w, smf.w * inv);
    gp[base1 + 0] = make_float4(mxm.x, smm.x * inv, mxm.y, smm.y * inv);
    gp[base1 + 1] = make_float4(mxm.z, smm.z * inv, mxm.w, smm.w * inv);
}

// ---------------------------------------------------------------------------
// Kernel 2: 7x7x7 conv (channel-paired f32x2, row-streamed) + sigmoid + apply
// Tile: 32(W) x 16(H) x 2(D), 128 threads (16,4,2), per-thread 2W x 4H x 1D
// 16-lane W split -> 16B lane stride -> conflict-free LDS.128, dense rows.
// 56.6 KB smem -> 4 CTAs/SM (16 warps).
// ---------------------------------------------------------------------------
constexpr int TW = 32, TH = 16, TD = 2;
constexpr int HXP = TW + 6;   // 38 pairs per halo row (304B, 16B-aligned)
constexpr int HY  = TH + 6;   // 22
constexpr int HZ  = TD + 6;   // 8
constexpr int HALO_P = HZ * HY * HXP;             // 6688 pairs = 53504 B
constexpr int W_ULLS = 7 * 7 * 8;                 // padded weights [kz][ky][8]
constexpr int SMEM_BYTES = HALO_P * 8 + W_ULLS * 8;   // 56640 B

__global__ void __launch_bounds__(128, 4)
conv_apply_kernel(const float* __restrict__ fix, const float* __restrict__ mov,
                  const float* __restrict__ w_f2m, const float* __restrict__ w_m2f,
                  float* __restrict__ out) {
    extern __shared__ float2 smem2[];
    float2* s_h  = smem2;                                   // [HZ][HY][HXP]
    ull*    s_w2 = reinterpret_cast<ull*>(smem2 + HALO_P);  // padded weight pairs

    const int tx = threadIdx.x;      // 0..15 (2 W outputs)
    const int ty = threadIdx.y;      // 0..3  (4 H outputs)
    const int tz = threadIdx.z;      // 0..1  (1 D output)
    const int tid = tx + ty * 16 + tz * 64;

    const int x0 = blockIdx.x * TW;
    const int y0 = blockIdx.y * TH;
    const int bz = blockIdx.z;                 // 0..79
    const int b  = bz / (D_ / TD);
    const int z0 = (bz - b * (D_ / TD)) * TD;

    const unsigned s_h_sa = (unsigned)__cvta_generic_to_shared(s_h);

    float gf[2][4], gm[2][4];   // sigmoid gates per gate, [w][h]

#pragma unroll 1
    for (int g = 0; g < 2; g++) {
        // ---- halo via cp.async (zfill for OOB) ----
        const float2* src = reinterpret_cast<const float2*>(g_pool)
                          + (size_t)g * SP + (size_t)b * DHW;
        for (int i = tid; i < HALO_P; i += 128) {
            int dz  = i / (HY * HXP);
            int rem = i - dz * (HY * HXP);
            int dy  = rem / HXP;
            int dx  = rem - dy * HXP;
            int gz = z0 + dz - 3, gy = y0 + dy - 3, gx = x0 + dx - 3;
            bool ok = ((unsigned)gz < (unsigned)D_) &&
                      ((unsigned)gy < (unsigned)H_) &&
                      ((unsigned)gx < (unsigned)W_);
            int off = ok ? ((gz * H_ + gy) * W_ + gx) : 0;
            unsigned sa = s_h_sa + (unsigned)(i * 8);
            int nb = ok ? 8 : 0;
            asm volatile("cp.async.ca.shared.global [%0], [%1], 8, %2;"
                         :: "r"(sa), "l"(src + off), "r"(nb));
        }
        asm volatile("cp.async.commit_group;" ::: "memory");

        // ---- paired weights into padded layout [kz][ky][8] ----
        const float* wsrc = (g == 0 ? w_f2m : w_m2f);
        for (int k = tid; k < 343; k += 128) {
            int kz  = k / 49;
            int rem = k - kz * 49;
            int ky  = rem / 7;
            int kx  = rem - ky * 7;
            reinterpret_cast<float2*>(s_w2)[kz * 56 + ky * 8 + kx] =
                make_float2(wsrc[k], wsrc[343 + k]);
        }
        asm volatile("cp.async.wait_group 0;" ::: "memory");
        __syncthreads();

        // ---- conv: stream rows, channel-paired FFMA2 ----
        ull pacc[2][4];   // [w][h]
#pragma unroll
        for (int w = 0; w < 2; w++)
#pragma unroll
            for (int h = 0; h < 4; h++) pacc[w][h] = 0ull;

#pragma unroll 1
        for (int kz = 0; kz < 7; kz++) {
            const float2* plane = s_h + (((size_t)tz + kz) * HY + ty * 4) * HXP + tx * 2;
            const ull*    wz    = s_w2 + kz * 56;
#pragma unroll
            for (int r = 0; r < 10; r++) {
                const float2* p = plane + r * HXP;
                // 8 pairs = 4 x LDS.128, lane stride 16B -> conflict-free
                ulonglong2 q0 = *reinterpret_cast<const ulonglong2*>(p);
                ulonglong2 q1 = *reinterpret_cast<const ulonglong2*>(p + 2);
                ulonglong2 q2 = *reinterpret_cast<const ulonglong2*>(p + 4);
                ulonglong2 q3 = *reinterpret_cast<const ulonglong2*>(p + 6);
                ull pk[8] = {q0.x, q0.y, q1.x, q1.y, q2.x, q2.y, q3.x, q3.y};
#pragma unroll
                for (int h = 0; h < 4; h++) {
                    const int ky = r - h;
                    if (ky >= 0 && ky <= 6) {
                        const ull* wr = wz + ky * 8;   // 16B-aligned row
                        ulonglong2 a0 = *reinterpret_cast<const ulonglong2*>(wr);
                        ulonglong2 a1 = *reinterpret_cast<const ulonglong2*>(wr + 2);
                        ulonglong2 a2 = *reinterpret_cast<const ulonglong2*>(wr + 4);
                        ull w6 = wr[6];
                        ull wk[7] = {a0.x, a0.y, a1.x, a1.y, a2.x, a2.y, w6};
#pragma unroll
                        for (int kx = 0; kx < 7; kx++) {
                            ull wv = wk[kx];
#pragma unroll
                            for (int w = 0; w < 2; w++)
                                fma2(pacc[w][h], pk[kx + w], wv);
                        }
                    }
                }
            }
        }

        // ---- reduce channel pair + sigmoid immediately (frees pacc regs) ----
#pragma unroll
        for (int w = 0; w < 2; w++)
#pragma unroll
            for (int h = 0; h < 4; h++) {
                float lo, hi;
                unpack2(lo, hi, pacc[w][h]);
                float s = 1.f / (1.f + __expf(-(lo + hi)));
                if (g == 0) gf[w][h] = s;
                else        gm[w][h] = s;
            }

        __syncthreads();   // protect smem before next gate overwrites
    }

    // ---- apply: fix_out = mov*sa_fix + fix ; move_out = fix*sa_move + mov ----
    const int z  = z0 + tz;
    const int yb = y0 + ty * 4;
    const int x  = x0 + tx * 2;
    const size_t sbase = (size_t)b * C_ * DHW + (size_t)z * H_ * W_ + (size_t)yb * W_ + x;
    float* out_f = out;
    float* out_m = out + TEN;

#pragma unroll 2
    for (int c = 0; c < C_; c++) {
        size_t oc = sbase + (size_t)c * DHW;
#pragma unroll
        for (int h = 0; h < 4; h++) {
            size_t o = oc + (size_t)h * W_;
            float2 f = *reinterpret_cast<const float2*>(fix + o);
            float2 m = *reinterpret_cast<const float2*>(mov + o);
            float2 of, om;
            of.x = fmaf(m.x, gf[0][h], f.x);  om.x = fmaf(f.x, gm[0][h], m.x);
            of.y = fmaf(m.y, gf[1][h], f.y);  om.y = fmaf(f.y, gm[1][h], m.y);
            *reinterpret_cast<float2*>(out_f + o) = of;
            *reinterpret_cast<float2*>(out_m + o) = om;
        }
    }
}

// ---------------------------------------------------------------------------
extern "C" void kernel_launch(void* const* d_in, const int* in_sizes, int n_in,
                              void* d_out, int out_size) {
    const float* fix   = (const float*)d_in[0];
    const float* mov   = (const float*)d_in[1];
    const float* w_f2m = (const float*)d_in[2];
    const float* w_m2f = (const float*)d_in[3];
    float* out = (float*)d_out;

    static bool attr_set = false;
    if (!attr_set) {
        cudaFuncSetAttribute(conv_apply_kernel,
                             cudaFuncAttributeMaxDynamicSharedMemorySize, SMEM_BYTES);
        attr_set = true;
    }

    // Pass 1: pooling (writes channel-interleaved pairs)
    {
        int threads = 256;
        int blocks = (SP / 4 + threads - 1) / threads;
        pool_kernel<<<blocks, threads>>>(fix, mov);
    }
    // Pass 2: conv + sigmoid + gated residual
    {
        dim3 block(16, 4, 2);                             // 128 threads
        dim3 grid(W_ / TW, H_ / TH, B_ * (D_ / TD));      // 3 x 6 x 80 = 1440
        conv_apply_kernel<<<grid, block, SMEM_BYTES>>>(fix, mov, w_f2m, w_m2f, out);
    }
}

// round 13
// speedup vs baseline: 1.1703x; 1.0019x over previous
#include <cuda_runtime.h>
#include <math.h>
#include <float.h>

// Problem shape (fixed by the reference)
constexpr int B_ = 2;
constexpr int C_ = 16;
constexpr int D_ = 80;
constexpr int H_ = 96;
constexpr int W_ = 96;
constexpr int DHW = D_ * H_ * W_;             // 737280
constexpr int SP  = B_ * DHW;                 // 1474560
constexpr size_t TEN = (size_t)B_ * C_ * DHW; // elements per tensor

// Scratch: per gate, interleaved {max, avg} pairs. (float2)[gate][b*DHW + pos]
__device__ float g_pool[4 * SP];

typedef unsigned long long ull;

__device__ __forceinline__ void unpack2(float& lo, float& hi, ull v) {
    asm("mov.b64 {%0, %1}, %2;" : "=f"(lo), "=f"(hi) : "l"(v));
}
// packed dual-fp32 FMA: d = a*b + d
__device__ __forceinline__ void fma2(ull& d, ull a, ull b) {
    asm("fma.rn.f32x2 %0, %1, %2, %0;" : "+l"(d) : "l"(a), "l"(b));
}

// ---------------------------------------------------------------------------
// Kernel 1: channel max/avg pooling, writes {max,avg} interleaved per gate
// ---------------------------------------------------------------------------
__global__ __launch_bounds__(256)
void pool_kernel(const float* __restrict__ fix, const float* __restrict__ mov) {
    int g4 = blockIdx.x * blockDim.x + threadIdx.x;   // group of 4 positions
    constexpr int Q = DHW / 4;
    if (g4 >= SP / 4) return;
    int b  = g4 / Q;
    int s4 = g4 - b * Q;

    const float4* pf = reinterpret_cast<const float4*>(fix) + (size_t)b * C_ * Q + s4;
    const float4* pm = reinterpret_cast<const float4*>(mov) + (size_t)b * C_ * Q + s4;

    float4 mxf = make_float4(-FLT_MAX, -FLT_MAX, -FLT_MAX, -FLT_MAX);
    float4 mxm = mxf;
    float4 smf = make_float4(0.f, 0.f, 0.f, 0.f);
    float4 smm = smf;
#pragma unroll
    for (int c = 0; c < C_; c++) {
        float4 v = pf[(size_t)c * Q];
        mxf.x = fmaxf(mxf.x, v.x); mxf.y = fmaxf(mxf.y, v.y);
        mxf.z = fmaxf(mxf.z, v.z); mxf.w = fmaxf(mxf.w, v.w);
        smf.x += v.x; smf.y += v.y; smf.z += v.z; smf.w += v.w;
        float4 u = pm[(size_t)c * Q];
        mxm.x = fmaxf(mxm.x, u.x); mxm.y = fmaxf(mxm.y, u.y);
        mxm.z = fmaxf(mxm.z, u.z); mxm.w = fmaxf(mxm.w, u.w);
        smm.x += u.x; smm.y += u.y; smm.z += u.z; smm.w += u.w;
    }
    const float inv = 1.f / 16.f;

    float4* gp = reinterpret_cast<float4*>(g_pool);
    size_t base0 = ((size_t)0 * SP + (size_t)b * DHW) / 2 + 2 * (size_t)s4;
    size_t base1 = ((size_t)1 * SP + (size_t)b * DHW) / 2 + 2 * (size_t)s4;
    gp[base0 + 0] = make_float4(mxf.x, smf.x * inv, mxf.y, smf.y * inv);
    gp[base0 + 1] = make_float4(mxf.z, smf.z * inv, mxf.w, smf.w * inv);
    gp[base1 + 0] = make_float4(mxm.x, smm.x * inv, mxm.y, smm.y * inv);
    gp[base1 + 1] = make_float4(mxm.z, smm.z * inv, mxm.w, smm.w * inv);
}

// ---------------------------------------------------------------------------
// Kernel 2: 7x7x7 conv (channel-paired f32x2, row-streamed) + sigmoid + apply
// Tile: 32(W) x 16(H) x 2(D), 128 threads (16,4,2), per-thread 2W x 4H x 1D
// 16-lane W split -> 16B lane stride -> conflict-free LDS.128, dense rows.
// 56.6 KB smem -> 4 CTAs/SM (16 warps).
// ---------------------------------------------------------------------------
constexpr int TW = 32, TH = 16, TD = 2;
constexpr int HXP = TW + 6;   // 38 pairs per halo row (304B, 16B-aligned)
constexpr int HY  = TH + 6;   // 22
constexpr int HZ  = TD + 6;   // 8
constexpr int HALO_P = HZ * HY * HXP;             // 6688 pairs = 53504 B
constexpr int W_ULLS = 7 * 7 * 8;                 // padded weights [kz][ky][8]
constexpr int SMEM_BYTES = HALO_P * 8 + W_ULLS * 8;   // 56640 B

__global__ void __launch_bounds__(128, 4)
conv_apply_kernel(const float* __restrict__ fix, const float* __restrict__ mov,
                  const float* __restrict__ w_f2m, const float* __restrict__ w_m2f,
                  float* __restrict__ out) {
    extern __shared__ float2 smem2[];
    float2* s_h  = smem2;                                   // [HZ][HY][HXP]
    ull*    s_w2 = reinterpret_cast<ull*>(smem2 + HALO_P);  // padded weight pairs

    const int tx = threadIdx.x;      // 0..15 (2 W outputs)
    const int ty = threadIdx.y;      // 0..3  (4 H outputs)
    const int tz = threadIdx.z;      // 0..1  (1 D output)
    const int tid = tx + ty * 16 + tz * 64;

    const int x0 = blockIdx.x * TW;
    const int y0 = blockIdx.y * TH;
    const int bz = blockIdx.z;                 // 0..79
    const int b  = bz / (D_ / TD);
    const int z0 = (bz - b * (D_ / TD)) * TD;

    const unsigned s_h_sa = (unsigned)__cvta_generic_to_shared(s_h);

    float gf[2][4], gm[2][4];   // sigmoid gates per gate, [w][h]

#pragma unroll 1
    for (int g = 0; g < 2; g++) {
        // ---- halo via cp.async (zfill for OOB) ----
        const float2* src = reinterpret_cast<const float2*>(g_pool)
                          + (size_t)g * SP + (size_t)b * DHW;
        for (int i = tid; i < HALO_P; i += 128) {
            int dz  = i / (HY * HXP);
            int rem = i - dz * (HY * HXP);
            int dy  = rem / HXP;
            int dx  = rem - dy * HXP;
            int gz = z0 + dz - 3, gy = y0 + dy - 3, gx = x0 + dx - 3;
            bool ok = ((unsigned)gz < (unsigned)D_) &&
                      ((unsigned)gy < (unsigned)H_) &&
                      ((unsigned)gx < (unsigned)W_);
            int off = ok ? ((gz * H_ + gy) * W_ + gx) : 0;
            unsigned sa = s_h_sa + (unsigned)(i * 8);
            int nb = ok ? 8 : 0;
            asm volatile("cp.async.ca.shared.global [%0], [%1], 8, %2;"
                         :: "r"(sa), "l"(src + off), "r"(nb));
        }
        asm volatile("cp.async.commit_group;" ::: "memory");

        // ---- paired weights into padded layout [kz][ky][8] ----
        const float* wsrc = (g == 0 ? w_f2m : w_m2f);
        for (int k = tid; k < 343; k += 128) {
            int kz  = k / 49;
            int rem = k - kz * 49;
            int ky  = rem / 7;
            int kx  = rem - ky * 7;
            reinterpret_cast<float2*>(s_w2)[kz * 56 + ky * 8 + kx] =
                make_float2(wsrc[k], wsrc[343 + k]);
        }
        asm volatile("cp.async.wait_group 0;" ::: "memory");
        __syncthreads();

        // ---- conv: stream rows, channel-paired FFMA2 ----
        ull pacc[2][4];   // [w][h]
#pragma unroll
        for (int w = 0; w < 2; w++)
#pragma unroll
            for (int h = 0; h < 4; h++) pacc[w][h] = 0ull;

#pragma unroll 1
        for (int kz = 0; kz < 7; kz++) {
            const float2* plane = s_h + (((size_t)tz + kz) * HY + ty * 4) * HXP + tx * 2;
            const ull*    wz    = s_w2 + kz * 56;
#pragma unroll
            for (int r = 0; r < 10; r++) {
                const float2* p = plane + r * HXP;
                // 8 pairs = 4 x LDS.128, lane stride 16B -> conflict-free
                ulonglong2 q0 = *reinterpret_cast<const ulonglong2*>(p);
                ulonglong2 q1 = *reinterpret_cast<const ulonglong2*>(p + 2);
                ulonglong2 q2 = *reinterpret_cast<const ulonglong2*>(p + 4);
                ulonglong2 q3 = *reinterpret_cast<const ulonglong2*>(p + 6);
                ull pk[8] = {q0.x, q0.y, q1.x, q1.y, q2.x, q2.y, q3.x, q3.y};
#pragma unroll
                for (int h = 0; h < 4; h++) {
                    const int ky = r - h;
                    if (ky >= 0 && ky <= 6) {
                        const ull* wr = wz + ky * 8;   // 16B-aligned row
                        ulonglong2 a0 = *reinterpret_cast<const ulonglong2*>(wr);
                        ulonglong2 a1 = *reinterpret_cast<const ulonglong2*>(wr + 2);
                        ulonglong2 a2 = *reinterpret_cast<const ulonglong2*>(wr + 4);
                        ull w6 = wr[6];
                        ull wk[7] = {a0.x, a0.y, a1.x, a1.y, a2.x, a2.y, w6};
#pragma unroll
                        for (int kx = 0; kx < 7; kx++) {
                            ull wv = wk[kx];
#pragma unroll
                            for (int w = 0; w < 2; w++)
                                fma2(pacc[w][h], pk[kx + w], wv);
                        }
                    }
                }
            }
        }

        // ---- reduce channel pair + sigmoid immediately (frees pacc regs) ----
#pragma unroll
        for (int w = 0; w < 2; w++)
#pragma unroll
            for (int h = 0; h < 4; h++) {
                float lo, hi;
                unpack2(lo, hi, pacc[w][h]);
                float s = 1.f / (1.f + __expf(-(lo + hi)));
                if (g == 0) gf[w][h] = s;
                else        gm[w][h] = s;
            }

        __syncthreads();   // protect smem before next gate overwrites
    }

    // ---- apply: fix_out = mov*sa_fix + fix ; move_out = fix*sa_move + mov ----
    const int z  = z0 + tz;
    const int yb = y0 + ty * 4;
    const int x  = x0 + tx * 2;
    const size_t sbase = (size_t)b * C_ * DHW + (size_t)z * H_ * W_ + (size_t)yb * W_ + x;
    float* out_f = out;
    float* out_m = out + TEN;

#pragma unroll 2
    for (int c = 0; c < C_; c++) {
        size_t oc = sbase + (size_t)c * DHW;
#pragma unroll
        for (int h = 0; h < 4; h++) {
            size_t o = oc + (size_t)h * W_;
            float2 f = *reinterpret_cast<const float2*>(fix + o);
            float2 m = *reinterpret_cast<const float2*>(mov + o);
            float2 of, om;
            of.x = fmaf(m.x, gf[0][h], f.x);  om.x = fmaf(f.x, gm[0][h], m.x);
            of.y = fmaf(m.y, gf[1][h], f.y);  om.y = fmaf(f.y, gm[1][h], m.y);
            *reinterpret_cast<float2*>(out_f + o) = of;
            *reinterpret_cast<float2*>(out_m + o) = om;
        }
    }
}

// ---------------------------------------------------------------------------
extern "C" void kernel_launch(void* const* d_in, const int* in_sizes, int n_in,
                              void* d_out, int out_size) {
    const float* fix   = (const float*)d_in[0];
    const float* mov   = (const float*)d_in[1];
    const float* w_f2m = (const float*)d_in[2];
    const float* w_m2f = (const float*)d_in[3];
    float* out = (float*)d_out;

    static bool attr_set = false;
    if (!attr_set) {
        cudaFuncSetAttribute(conv_apply_kernel,
                             cudaFuncAttributeMaxDynamicSharedMemorySize, SMEM_BYTES);
        attr_set = true;
    }

    // Pass 1: pooling (writes channel-interleaved pairs)
    {
        int threads = 256;
        int blocks = (SP / 4 + threads - 1) / threads;
        pool_kernel<<<blocks, threads>>>(fix, mov);
    }
    // Pass 2: conv + sigmoid + gated residual
    {
        dim3 block(16, 4, 2);                             // 128 threads
        dim3 grid(W_ / TW, H_ / TH, B_ * (D_ / TD));      // 3 x 6 x 80 = 1440
        conv_apply_kernel<<<grid, block, SMEM_BYTES>>>(fix, mov, w_f2m, w_m2f, out);
    }
}